// round 1
// baseline (speedup 1.0000x reference)
#include <cuda_runtime.h>
#include <math.h>

#define NB 4096
#define NS 64
#define NY 256
#define NH 128
#define NE 32
#define NKG 8
#define NKA 20
#define NNC 50
#define NNT 5

__global__ __launch_bounds__(256) void wine_kernel(
    const float* __restrict__ x_enc,
    const int*   __restrict__ grapes,
    const float* __restrict__ grapes_scales,
    const int*   __restrict__ aromas,
    const float* __restrict__ aromas_scales,
    const float* __restrict__ W_common, const float* __restrict__ b_common,
    const float* __restrict__ W_country, const float* __restrict__ b_country,
    const float* __restrict__ W_type,   const float* __restrict__ b_type,
    const float* __restrict__ W_taste,  const float* __restrict__ b_taste,
    const float* __restrict__ W_aroma,  const float* __restrict__ b_aroma,
    const float* __restrict__ W_grape,  const float* __restrict__ b_grape,
    const float* __restrict__ grapes_emb,
    const float* __restrict__ aroma_emb,
    float* __restrict__ out)
{
    __shared__ __align__(16) float x_sm[NY];
    __shared__ float y_sm[NH];
    __shared__ __align__(16) float yg_sm[NE];
    __shared__ __align__(16) float ya_sm[NE];
    __shared__ float4 part4[4][64];

    const int b    = blockIdx.x;
    const int tid  = threadIdx.x;
    const int col4 = tid & 63;   // which float4 of the 256-wide row
    const int sgrp = tid >> 6;   // 0..3, strided slice of the 64 seq rows

    // ---------- Phase 1: max over sequence dim (the 268 MB stream) ----------
    const float4* xe4 = reinterpret_cast<const float4*>(x_enc)
                      + (size_t)b * (NS * NY / 4);
    float4 m = make_float4(-INFINITY, -INFINITY, -INFINITY, -INFINITY);
    #pragma unroll
    for (int s = sgrp; s < NS; s += 4) {
        float4 v = xe4[s * (NY / 4) + col4];
        m.x = fmaxf(m.x, v.x); m.y = fmaxf(m.y, v.y);
        m.z = fmaxf(m.z, v.z); m.w = fmaxf(m.w, v.w);
    }
    part4[sgrp][col4] = m;
    __syncthreads();
    if (tid < 64) {
        float4 a = part4[0][tid], c = part4[1][tid];
        float4 d = part4[2][tid], e = part4[3][tid];
        float4 r;
        r.x = fmaxf(fmaxf(a.x, c.x), fmaxf(d.x, e.x));
        r.y = fmaxf(fmaxf(a.y, c.y), fmaxf(d.y, e.y));
        r.z = fmaxf(fmaxf(a.z, c.z), fmaxf(d.z, e.z));
        r.w = fmaxf(fmaxf(a.w, c.w), fmaxf(d.w, e.w));
        reinterpret_cast<float4*>(x_sm)[tid] = r;
    }
    __syncthreads();

    // ---------- Phase 2: y = elu(x @ W_common + b_common), [256]->[128] ----------
    if (tid < NH) {
        float acc = b_common[tid];
        #pragma unroll 8
        for (int i = 0; i < NY; i++)
            acc = fmaf(x_sm[i], W_common[i * NH + tid], acc);
        y_sm[tid] = (acc > 0.f) ? acc : (expf(acc) - 1.f);
    }
    __syncthreads();

    // ---------- Phase 3: heads (120 dot-128 products, one per thread) ----------
    if (tid < NNC) {
        float acc = b_country[tid];
        #pragma unroll 8
        for (int h = 0; h < NH; h++)
            acc = fmaf(y_sm[h], W_country[h * NNC + tid], acc);
        out[(size_t)b * NNC + tid] = acc;                       // y_country (no act)
    } else if (tid == NNC) {
        float acc = b_type[0];
        #pragma unroll 8
        for (int h = 0; h < NH; h++)
            acc = fmaf(y_sm[h], W_type[h], acc);
        out[(size_t)NB * NNC + b] = 1.f / (1.f + expf(-acc));   // y_type
    } else if (tid < 56) {
        int c = tid - 51;
        float acc = b_taste[c];
        #pragma unroll 8
        for (int h = 0; h < NH; h++)
            acc = fmaf(y_sm[h], W_taste[h * NNT + c], acc);
        out[(size_t)NB * 51 + (size_t)b * NNT + c] = 1.f / (1.f + expf(-acc));
    } else if (tid < 88) {
        int e = tid - 56;
        float acc = b_grape[e];
        #pragma unroll 8
        for (int h = 0; h < NH; h++)
            acc = fmaf(y_sm[h], W_grape[h * NE + e], acc);
        yg_sm[e] = acc;                                         // y_grape
    } else if (tid < 120) {
        int e = tid - 88;
        float acc = b_aroma[e];
        #pragma unroll 8
        for (int h = 0; h < NH; h++)
            acc = fmaf(y_sm[h], W_aroma[h * NE + e], acc);
        ya_sm[e] = acc;                                         // y_aromas
    }
    __syncthreads();

    // ---------- Phase 4: ragged embedding-slot scoring ----------
    if (tid < NKG) {
        int   idx = grapes[b * NKG + tid];
        float sc  = grapes_scales[b * NKG + tid];
        const float4* emb = reinterpret_cast<const float4*>(grapes_emb)
                          + (size_t)idx * (NE / 4);
        const float4* yg4 = reinterpret_cast<const float4*>(yg_sm);
        float acc = 0.f;
        #pragma unroll
        for (int i = 0; i < NE / 4; i++) {
            float4 ev = emb[i], yv = yg4[i];
            acc += ev.x * yv.x + ev.y * yv.y + ev.z * yv.z + ev.w * yv.w;
        }
        float mask = (idx != 0) ? 1.f : 0.f;
        out[(size_t)NB * 56 + (size_t)b * NKG + tid] =
            (1.f / (1.f + expf(-acc))) * mask;                  // grape_pred
        out[(size_t)NB * 64 + (size_t)b * NKG + tid] = sc;      // grape_true
    } else if (tid < NKG + NKA) {
        int   k   = tid - NKG;
        int   idx = aromas[b * NKA + k];
        float sc  = aromas_scales[b * NKA + k];
        const float4* emb = reinterpret_cast<const float4*>(aroma_emb)
                          + (size_t)idx * (NE / 4);
        const float4* ya4 = reinterpret_cast<const float4*>(ya_sm);
        float acc = 0.f;
        #pragma unroll
        for (int i = 0; i < NE / 4; i++) {
            float4 ev = emb[i], yv = ya4[i];
            acc += ev.x * yv.x + ev.y * yv.y + ev.z * yv.z + ev.w * yv.w;
        }
        float mask = (sc != 0.f) ? 1.f : 0.f;
        out[(size_t)NB * 72 + (size_t)b * NKA + k] =
            (1.f / (1.f + expf(-acc))) * mask;                  // aroma_pred
        out[(size_t)NB * 92 + (size_t)b * NKA + k] = sc;        // aroma_true (sc*mask==sc)
    }
}

extern "C" void kernel_launch(void* const* d_in, const int* in_sizes, int n_in,
                              void* d_out, int out_size) {
    const float* x_enc          = (const float*)d_in[0];
    const int*   grapes         = (const int*)  d_in[1];
    const float* grapes_scales  = (const float*)d_in[2];
    const int*   aromas         = (const int*)  d_in[3];
    const float* aromas_scales  = (const float*)d_in[4];
    const float* W_common       = (const float*)d_in[5];
    const float* b_common       = (const float*)d_in[6];
    const float* W_country      = (const float*)d_in[7];
    const float* b_country      = (const float*)d_in[8];
    const float* W_type         = (const float*)d_in[9];
    const float* b_type         = (const float*)d_in[10];
    const float* W_taste        = (const float*)d_in[11];
    const float* b_taste        = (const float*)d_in[12];
    const float* W_aroma        = (const float*)d_in[13];
    const float* b_aroma        = (const float*)d_in[14];
    const float* W_grape        = (const float*)d_in[15];
    const float* b_grape        = (const float*)d_in[16];
    const float* grapes_emb     = (const float*)d_in[17];
    const float* aroma_emb      = (const float*)d_in[18];
    float* out = (float*)d_out;

    wine_kernel<<<NB, 256>>>(x_enc, grapes, grapes_scales, aromas, aromas_scales,
                             W_common, b_common, W_country, b_country,
                             W_type, b_type, W_taste, b_taste,
                             W_aroma, b_aroma, W_grape, b_grape,
                             grapes_emb, aroma_emb, out);
}

// round 2
// speedup vs baseline: 1.3083x; 1.3083x over previous
#include <cuda_runtime.h>
#include <math.h>

#define NB 4096
#define NS 64
#define NY 256
#define NH 128
#define NE 32
#define NKG 8
#define NKA 20
#define NNC 50
#define NNT 5

// scratch: pooled x [B, Y] as float4
__device__ float4 d_xmax4[NB * (NY / 4)];

// ---------------- Kernel A: max over seq dim (pure 268MB stream) ----------------
__global__ __launch_bounds__(256) void maxpool_k(const float4* __restrict__ x4)
{
    int t  = blockIdx.x * 256 + threadIdx.x;   // 0 .. B*64-1
    int b  = t >> 6;
    int c4 = t & 63;
    const float4* p = x4 + (size_t)b * (NS * NY / 4) + c4;

    float4 m0 = p[0 * 64], m1 = p[1 * 64], m2 = p[2 * 64], m3 = p[3 * 64];
    #pragma unroll
    for (int s = 4; s < NS; s += 4) {
        float4 v0 = p[(s + 0) * 64];
        float4 v1 = p[(s + 1) * 64];
        float4 v2 = p[(s + 2) * 64];
        float4 v3 = p[(s + 3) * 64];
        m0.x = fmaxf(m0.x, v0.x); m0.y = fmaxf(m0.y, v0.y); m0.z = fmaxf(m0.z, v0.z); m0.w = fmaxf(m0.w, v0.w);
        m1.x = fmaxf(m1.x, v1.x); m1.y = fmaxf(m1.y, v1.y); m1.z = fmaxf(m1.z, v1.z); m1.w = fmaxf(m1.w, v1.w);
        m2.x = fmaxf(m2.x, v2.x); m2.y = fmaxf(m2.y, v2.y); m2.z = fmaxf(m2.z, v2.z); m2.w = fmaxf(m2.w, v2.w);
        m3.x = fmaxf(m3.x, v3.x); m3.y = fmaxf(m3.y, v3.y); m3.z = fmaxf(m3.z, v3.z); m3.w = fmaxf(m3.w, v3.w);
    }
    float4 r;
    r.x = fmaxf(fmaxf(m0.x, m1.x), fmaxf(m2.x, m3.x));
    r.y = fmaxf(fmaxf(m0.y, m1.y), fmaxf(m2.y, m3.y));
    r.z = fmaxf(fmaxf(m0.z, m1.z), fmaxf(m2.z, m3.z));
    r.w = fmaxf(fmaxf(m0.w, m1.w), fmaxf(m2.w, m3.w));
    d_xmax4[t] = r;
}

__device__ __forceinline__ float sigmoidf_(float v) { return 1.f / (1.f + expf(-v)); }

// ---------------- Kernel B: MLP + heads + ragged embedding scoring ----------------
// One block = 8 batch rows, 128 threads.
__global__ __launch_bounds__(128) void mlp_heads_k(
    const int*   __restrict__ grapes,
    const float* __restrict__ grapes_scales,
    const int*   __restrict__ aromas,
    const float* __restrict__ aromas_scales,
    const float* __restrict__ W_common, const float* __restrict__ b_common,
    const float* __restrict__ W_country, const float* __restrict__ b_country,
    const float* __restrict__ W_type,   const float* __restrict__ b_type,
    const float* __restrict__ W_taste,  const float* __restrict__ b_taste,
    const float* __restrict__ W_aroma,  const float* __restrict__ b_aroma,
    const float* __restrict__ W_grape,  const float* __restrict__ b_grape,
    const float* __restrict__ grapes_emb,
    const float* __restrict__ aroma_emb,
    float* __restrict__ out)
{
    __shared__ __align__(16) float x_sm[8 * NY];    // 8KB
    __shared__ __align__(16) float y_sm[8 * NH];    // 4KB
    __shared__ __align__(16) float yg_sm[8 * NE];   // 1KB
    __shared__ __align__(16) float ya_sm[8 * NE];   // 1KB

    const int t  = threadIdx.x;     // 0..127
    const int b0 = blockIdx.x * 8;

    // load x tile [8,256] (float4 coalesced, 4 per thread)
    const float4* xm4 = d_xmax4 + (size_t)b0 * (NY / 4);
    #pragma unroll
    for (int i = 0; i < 4; i++)
        reinterpret_cast<float4*>(x_sm)[t + i * 128] = xm4[t + i * 128];
    __syncthreads();

    // ---- GEMM: y[8][128] = elu(x[8][256] @ W_common + b) ; thread t owns column h=t ----
    {
        float acc[8];
        float bc = b_common[t];
        #pragma unroll
        for (int j = 0; j < 8; j++) acc[j] = bc;
        for (int i = 0; i < NY; i += 4) {
            float w0 = W_common[(i + 0) * NH + t];
            float w1 = W_common[(i + 1) * NH + t];
            float w2 = W_common[(i + 2) * NH + t];
            float w3 = W_common[(i + 3) * NH + t];
            #pragma unroll
            for (int j = 0; j < 8; j++) {
                float4 xv = *reinterpret_cast<const float4*>(&x_sm[j * NY + i]);
                acc[j] = fmaf(xv.x, w0, fmaf(xv.y, w1, fmaf(xv.z, w2, fmaf(xv.w, w3, acc[j]))));
            }
        }
        #pragma unroll
        for (int j = 0; j < 8; j++) {
            float a = acc[j];
            y_sm[j * NH + t] = (a > 0.f) ? a : expm1f(a);
        }
    }
    __syncthreads();

    // ---- heads: disjoint thread groups, each thread does 8 rows of one output col ----
    {
        float hacc[8];
        if (t < NNC) {                       // country, no activation
            float bb = b_country[t];
            #pragma unroll
            for (int j = 0; j < 8; j++) hacc[j] = bb;
            for (int i = 0; i < NH; i += 4) {
                float w0 = W_country[(i + 0) * NNC + t];
                float w1 = W_country[(i + 1) * NNC + t];
                float w2 = W_country[(i + 2) * NNC + t];
                float w3 = W_country[(i + 3) * NNC + t];
                #pragma unroll
                for (int j = 0; j < 8; j++) {
                    float4 yv = *reinterpret_cast<const float4*>(&y_sm[j * NH + i]);
                    hacc[j] = fmaf(yv.x, w0, fmaf(yv.y, w1, fmaf(yv.z, w2, fmaf(yv.w, w3, hacc[j]))));
                }
            }
            #pragma unroll
            for (int j = 0; j < 8; j++)
                out[(size_t)(b0 + j) * NNC + t] = hacc[j];
        } else if (t == NNC) {               // type, sigmoid
            float bb = b_type[0];
            #pragma unroll
            for (int j = 0; j < 8; j++) hacc[j] = bb;
            for (int i = 0; i < NH; i += 4) {
                float w0 = W_type[i + 0], w1 = W_type[i + 1], w2 = W_type[i + 2], w3 = W_type[i + 3];
                #pragma unroll
                for (int j = 0; j < 8; j++) {
                    float4 yv = *reinterpret_cast<const float4*>(&y_sm[j * NH + i]);
                    hacc[j] = fmaf(yv.x, w0, fmaf(yv.y, w1, fmaf(yv.z, w2, fmaf(yv.w, w3, hacc[j]))));
                }
            }
            #pragma unroll
            for (int j = 0; j < 8; j++)
                out[(size_t)NB * NNC + (b0 + j)] = sigmoidf_(hacc[j]);
        } else if (t < 56) {                 // taste, sigmoid
            int c = t - 51;
            float bb = b_taste[c];
            #pragma unroll
            for (int j = 0; j < 8; j++) hacc[j] = bb;
            for (int i = 0; i < NH; i += 4) {
                float w0 = W_taste[(i + 0) * NNT + c];
                float w1 = W_taste[(i + 1) * NNT + c];
                float w2 = W_taste[(i + 2) * NNT + c];
                float w3 = W_taste[(i + 3) * NNT + c];
                #pragma unroll
                for (int j = 0; j < 8; j++) {
                    float4 yv = *reinterpret_cast<const float4*>(&y_sm[j * NH + i]);
                    hacc[j] = fmaf(yv.x, w0, fmaf(yv.y, w1, fmaf(yv.z, w2, fmaf(yv.w, w3, hacc[j]))));
                }
            }
            #pragma unroll
            for (int j = 0; j < 8; j++)
                out[(size_t)NB * 51 + (size_t)(b0 + j) * NNT + c] = sigmoidf_(hacc[j]);
        } else if (t < 88) {                 // y_grape -> smem
            int e = t - 56;
            float bb = b_grape[e];
            #pragma unroll
            for (int j = 0; j < 8; j++) hacc[j] = bb;
            for (int i = 0; i < NH; i += 4) {
                float w0 = W_grape[(i + 0) * NE + e];
                float w1 = W_grape[(i + 1) * NE + e];
                float w2 = W_grape[(i + 2) * NE + e];
                float w3 = W_grape[(i + 3) * NE + e];
                #pragma unroll
                for (int j = 0; j < 8; j++) {
                    float4 yv = *reinterpret_cast<const float4*>(&y_sm[j * NH + i]);
                    hacc[j] = fmaf(yv.x, w0, fmaf(yv.y, w1, fmaf(yv.z, w2, fmaf(yv.w, w3, hacc[j]))));
                }
            }
            #pragma unroll
            for (int j = 0; j < 8; j++) yg_sm[j * NE + e] = hacc[j];
        } else if (t < 120) {                // y_aromas -> smem
            int e = t - 88;
            float bb = b_aroma[e];
            #pragma unroll
            for (int j = 0; j < 8; j++) hacc[j] = bb;
            for (int i = 0; i < NH; i += 4) {
                float w0 = W_aroma[(i + 0) * NE + e];
                float w1 = W_aroma[(i + 1) * NE + e];
                float w2 = W_aroma[(i + 2) * NE + e];
                float w3 = W_aroma[(i + 3) * NE + e];
                #pragma unroll
                for (int j = 0; j < 8; j++) {
                    float4 yv = *reinterpret_cast<const float4*>(&y_sm[j * NH + i]);
                    hacc[j] = fmaf(yv.x, w0, fmaf(yv.y, w1, fmaf(yv.z, w2, fmaf(yv.w, w3, hacc[j]))));
                }
            }
            #pragma unroll
            for (int j = 0; j < 8; j++) ya_sm[j * NE + e] = hacc[j];
        }
    }
    __syncthreads();

    // ---- ragged embedding scoring ----
    // grapes: 8 rows x 8 slots = 64 tasks
    if (t < 64) {
        int r = t >> 3, k = t & 7;
        int b = b0 + r;
        int   idx = grapes[b * NKG + k];
        float sc  = grapes_scales[b * NKG + k];
        const float4* emb = reinterpret_cast<const float4*>(grapes_emb) + (size_t)idx * (NE / 4);
        const float4* yv4 = reinterpret_cast<const float4*>(&yg_sm[r * NE]);
        float acc = 0.f;
        #pragma unroll
        for (int i = 0; i < NE / 4; i++) {
            float4 ev = emb[i], yv = yv4[i];
            acc += ev.x * yv.x + ev.y * yv.y + ev.z * yv.z + ev.w * yv.w;
        }
        float mask = (idx != 0) ? 1.f : 0.f;
        out[(size_t)NB * 56 + (size_t)b * NKG + k] = sigmoidf_(acc) * mask;
        out[(size_t)NB * 64 + (size_t)b * NKG + k] = sc;
    }
    // aromas: 8 rows x 20 slots = 160 tasks
    for (int task = t; task < 8 * NKA; task += 128) {
        int r = task / NKA, k = task % NKA;
        int b = b0 + r;
        int   idx = aromas[b * NKA + k];
        float sc  = aromas_scales[b * NKA + k];
        const float4* emb = reinterpret_cast<const float4*>(aroma_emb) + (size_t)idx * (NE / 4);
        const float4* yv4 = reinterpret_cast<const float4*>(&ya_sm[r * NE]);
        float acc = 0.f;
        #pragma unroll
        for (int i = 0; i < NE / 4; i++) {
            float4 ev = emb[i], yv = yv4[i];
            acc += ev.x * yv.x + ev.y * yv.y + ev.z * yv.z + ev.w * yv.w;
        }
        float mask = (sc != 0.f) ? 1.f : 0.f;
        out[(size_t)NB * 72 + (size_t)b * NKA + k] = sigmoidf_(acc) * mask;
        out[(size_t)NB * 92 + (size_t)b * NKA + k] = sc;
    }
}

extern "C" void kernel_launch(void* const* d_in, const int* in_sizes, int n_in,
                              void* d_out, int out_size) {
    const float* x_enc          = (const float*)d_in[0];
    const int*   grapes         = (const int*)  d_in[1];
    const float* grapes_scales  = (const float*)d_in[2];
    const int*   aromas         = (const int*)  d_in[3];
    const float* aromas_scales  = (const float*)d_in[4];
    const float* W_common       = (const float*)d_in[5];
    const float* b_common       = (const float*)d_in[6];
    const float* W_country      = (const float*)d_in[7];
    const float* b_country      = (const float*)d_in[8];
    const float* W_type         = (const float*)d_in[9];
    const float* b_type         = (const float*)d_in[10];
    const float* W_taste        = (const float*)d_in[11];
    const float* b_taste        = (const float*)d_in[12];
    const float* W_aroma        = (const float*)d_in[13];
    const float* b_aroma        = (const float*)d_in[14];
    const float* W_grape        = (const float*)d_in[15];
    const float* b_grape        = (const float*)d_in[16];
    const float* grapes_emb     = (const float*)d_in[17];
    const float* aroma_emb      = (const float*)d_in[18];
    float* out = (float*)d_out;

    maxpool_k<<<NB * (NY / 4) / 256, 256>>>(reinterpret_cast<const float4*>(x_enc));
    mlp_heads_k<<<NB / 8, 128>>>(grapes, grapes_scales, aromas, aromas_scales,
                                 W_common, b_common, W_country, b_country,
                                 W_type, b_type, W_taste, b_taste,
                                 W_aroma, b_aroma, W_grape, b_grape,
                                 grapes_emb, aroma_emb, out);
}

// round 3
// speedup vs baseline: 1.8834x; 1.4396x over previous
#include <cuda_runtime.h>
#include <math.h>

#define NB 4096
#define NS 64
#define NY 256
#define NH 128
#define NE 32
#define NKG 8
#define NKA 20
#define NNC 50
#define NNT 5

__device__ __forceinline__ float sigmoidf_(float v) { return 1.f / (1.f + expf(-v)); }

// One block = 8 batch rows, 512 threads.
__global__ __launch_bounds__(512, 2) void wine_fused(
    const float4* __restrict__ x4,
    const int*   __restrict__ grapes,
    const float* __restrict__ grapes_scales,
    const int*   __restrict__ aromas,
    const float* __restrict__ aromas_scales,
    const float* __restrict__ W_common, const float* __restrict__ b_common,
    const float* __restrict__ W_country, const float* __restrict__ b_country,
    const float* __restrict__ W_type,   const float* __restrict__ b_type,
    const float* __restrict__ W_taste,  const float* __restrict__ b_taste,
    const float* __restrict__ W_aroma,  const float* __restrict__ b_aroma,
    const float* __restrict__ W_grape,  const float* __restrict__ b_grape,
    const float* __restrict__ grapes_emb,
    const float* __restrict__ aroma_emb,
    float* __restrict__ out)
{
    __shared__ __align__(16) float x_sm[8 * NY];       // 8 KB
    __shared__ float red[4][128][9];                   // 18.4 KB, padded banks
    __shared__ __align__(16) float y_sm[8 * NH];       // 4 KB
    __shared__ __align__(16) float yg_sm[8 * NE];      // 1 KB
    __shared__ __align__(16) float ya_sm[8 * NE];      // 1 KB

    const int tid = threadIdx.x;
    const int b0  = blockIdx.x * 8;

    // ---------- Phase 1: max-pool. thread = (row r, float4-col c4), private over seq ----------
    {
        const int r  = tid >> 6;    // 0..7
        const int c4 = tid & 63;    // 0..63
        const float4* p = x4 + (size_t)(b0 + r) * (NS * NY / 4) + c4;
        float4 m0 = p[0 * 64], m1 = p[1 * 64], m2 = p[2 * 64], m3 = p[3 * 64];
        #pragma unroll
        for (int s = 4; s < NS; s += 4) {
            float4 v0 = p[(s + 0) * 64];
            float4 v1 = p[(s + 1) * 64];
            float4 v2 = p[(s + 2) * 64];
            float4 v3 = p[(s + 3) * 64];
            m0.x = fmaxf(m0.x, v0.x); m0.y = fmaxf(m0.y, v0.y); m0.z = fmaxf(m0.z, v0.z); m0.w = fmaxf(m0.w, v0.w);
            m1.x = fmaxf(m1.x, v1.x); m1.y = fmaxf(m1.y, v1.y); m1.z = fmaxf(m1.z, v1.z); m1.w = fmaxf(m1.w, v1.w);
            m2.x = fmaxf(m2.x, v2.x); m2.y = fmaxf(m2.y, v2.y); m2.z = fmaxf(m2.z, v2.z); m2.w = fmaxf(m2.w, v2.w);
            m3.x = fmaxf(m3.x, v3.x); m3.y = fmaxf(m3.y, v3.y); m3.z = fmaxf(m3.z, v3.z); m3.w = fmaxf(m3.w, v3.w);
        }
        float4 rr;
        rr.x = fmaxf(fmaxf(m0.x, m1.x), fmaxf(m2.x, m3.x));
        rr.y = fmaxf(fmaxf(m0.y, m1.y), fmaxf(m2.y, m3.y));
        rr.z = fmaxf(fmaxf(m0.z, m1.z), fmaxf(m2.z, m3.z));
        rr.w = fmaxf(fmaxf(m0.w, m1.w), fmaxf(m2.w, m3.w));
        reinterpret_cast<float4*>(x_sm)[r * (NY / 4) + c4] = rr;
    }
    __syncthreads();

    // ---------- Phase 2: GEMM1 y[8][128] = elu(x[8][256] @ W_common + b), split-K x4 ----------
    {
        const int h  = tid & 127;
        const int kq = tid >> 7;          // 0..3, owns K range [kq*64, kq*64+64)
        float acc[8];
        #pragma unroll
        for (int j = 0; j < 8; j++) acc[j] = 0.f;
        const int kb = kq * 64;
        for (int i0 = 0; i0 < 64; i0 += 4) {
            const int i = kb + i0;
            float w0 = W_common[(i + 0) * NH + h];
            float w1 = W_common[(i + 1) * NH + h];
            float w2 = W_common[(i + 2) * NH + h];
            float w3 = W_common[(i + 3) * NH + h];
            #pragma unroll
            for (int j = 0; j < 8; j++) {
                float4 xv = *reinterpret_cast<const float4*>(&x_sm[j * NY + i]);
                acc[j] = fmaf(xv.x, w0, fmaf(xv.y, w1, fmaf(xv.z, w2, fmaf(xv.w, w3, acc[j]))));
            }
        }
        #pragma unroll
        for (int j = 0; j < 8; j++) red[kq][h][j] = acc[j];
    }
    __syncthreads();
    if (tid < NH) {
        const int h = tid;
        float bb = b_common[h];
        #pragma unroll
        for (int j = 0; j < 8; j++) {
            float v = red[0][h][j] + red[1][h][j] + red[2][h][j] + red[3][h][j] + bb;
            y_sm[j * NH + h] = (v > 0.f) ? v : expm1f(v);
        }
    }
    __syncthreads();

    // ---------- Phase 3: all heads as one 128x120 GEMM, split-K x4 ----------
    {
        const int c  = tid & 127;
        const int kq = tid >> 7;
        const int kb = kq * 32;           // K range [kb, kb+32) of NH=128
        float acc[8];
        #pragma unroll
        for (int j = 0; j < 8; j++) acc[j] = 0.f;

        if (c < NNC) {
            for (int i = kb; i < kb + 32; i += 4) {
                float w0 = W_country[(i + 0) * NNC + c];
                float w1 = W_country[(i + 1) * NNC + c];
                float w2 = W_country[(i + 2) * NNC + c];
                float w3 = W_country[(i + 3) * NNC + c];
                #pragma unroll
                for (int j = 0; j < 8; j++) {
                    float4 yv = *reinterpret_cast<const float4*>(&y_sm[j * NH + i]);
                    acc[j] = fmaf(yv.x, w0, fmaf(yv.y, w1, fmaf(yv.z, w2, fmaf(yv.w, w3, acc[j]))));
                }
            }
        } else if (c == NNC) {
            for (int i = kb; i < kb + 32; i += 4) {
                float w0 = W_type[i + 0], w1 = W_type[i + 1], w2 = W_type[i + 2], w3 = W_type[i + 3];
                #pragma unroll
                for (int j = 0; j < 8; j++) {
                    float4 yv = *reinterpret_cast<const float4*>(&y_sm[j * NH + i]);
                    acc[j] = fmaf(yv.x, w0, fmaf(yv.y, w1, fmaf(yv.z, w2, fmaf(yv.w, w3, acc[j]))));
                }
            }
        } else if (c < 56) {
            const int cc = c - 51;
            for (int i = kb; i < kb + 32; i += 4) {
                float w0 = W_taste[(i + 0) * NNT + cc];
                float w1 = W_taste[(i + 1) * NNT + cc];
                float w2 = W_taste[(i + 2) * NNT + cc];
                float w3 = W_taste[(i + 3) * NNT + cc];
                #pragma unroll
                for (int j = 0; j < 8; j++) {
                    float4 yv = *reinterpret_cast<const float4*>(&y_sm[j * NH + i]);
                    acc[j] = fmaf(yv.x, w0, fmaf(yv.y, w1, fmaf(yv.z, w2, fmaf(yv.w, w3, acc[j]))));
                }
            }
        } else if (c < 88) {
            const int e = c - 56;
            for (int i = kb; i < kb + 32; i += 4) {
                float w0 = W_grape[(i + 0) * NE + e];
                float w1 = W_grape[(i + 1) * NE + e];
                float w2 = W_grape[(i + 2) * NE + e];
                float w3 = W_grape[(i + 3) * NE + e];
                #pragma unroll
                for (int j = 0; j < 8; j++) {
                    float4 yv = *reinterpret_cast<const float4*>(&y_sm[j * NH + i]);
                    acc[j] = fmaf(yv.x, w0, fmaf(yv.y, w1, fmaf(yv.z, w2, fmaf(yv.w, w3, acc[j]))));
                }
            }
        } else if (c < 120) {
            const int e = c - 88;
            for (int i = kb; i < kb + 32; i += 4) {
                float w0 = W_aroma[(i + 0) * NE + e];
                float w1 = W_aroma[(i + 1) * NE + e];
                float w2 = W_aroma[(i + 2) * NE + e];
                float w3 = W_aroma[(i + 3) * NE + e];
                #pragma unroll
                for (int j = 0; j < 8; j++) {
                    float4 yv = *reinterpret_cast<const float4*>(&y_sm[j * NH + i]);
                    acc[j] = fmaf(yv.x, w0, fmaf(yv.y, w1, fmaf(yv.z, w2, fmaf(yv.w, w3, acc[j]))));
                }
            }
        }
        if (c < 120) {
            #pragma unroll
            for (int j = 0; j < 8; j++) red[kq][c][j] = acc[j];
        }
    }
    __syncthreads();
    if (tid < 120) {
        const int c = tid;
        float s[8];
        #pragma unroll
        for (int j = 0; j < 8; j++)
            s[j] = red[0][c][j] + red[1][c][j] + red[2][c][j] + red[3][c][j];
        if (c < NNC) {
            float bb = b_country[c];
            #pragma unroll
            for (int j = 0; j < 8; j++)
                out[(size_t)(b0 + j) * NNC + c] = s[j] + bb;
        } else if (c == NNC) {
            float bb = b_type[0];
            #pragma unroll
            for (int j = 0; j < 8; j++)
                out[(size_t)NB * NNC + (b0 + j)] = sigmoidf_(s[j] + bb);
        } else if (c < 56) {
            const int cc = c - 51;
            float bb = b_taste[cc];
            #pragma unroll
            for (int j = 0; j < 8; j++)
                out[(size_t)NB * 51 + (size_t)(b0 + j) * NNT + cc] = sigmoidf_(s[j] + bb);
        } else if (c < 88) {
            const int e = c - 56;
            float bb = b_grape[e];
            #pragma unroll
            for (int j = 0; j < 8; j++) yg_sm[j * NE + e] = s[j] + bb;
        } else {
            const int e = c - 88;
            float bb = b_aroma[e];
            #pragma unroll
            for (int j = 0; j < 8; j++) ya_sm[j * NE + e] = s[j] + bb;
        }
    }
    __syncthreads();

    // ---------- Phase 4: ragged embedding scoring ----------
    if (tid < 64) {                               // 8 rows x 8 grape slots
        const int r = tid >> 3, k = tid & 7;
        const int b = b0 + r;
        const int   idx = grapes[b * NKG + k];
        const float sc  = grapes_scales[b * NKG + k];
        const float4* emb = reinterpret_cast<const float4*>(grapes_emb) + (size_t)idx * (NE / 4);
        const float4* yv4 = reinterpret_cast<const float4*>(&yg_sm[r * NE]);
        float acc = 0.f;
        #pragma unroll
        for (int i = 0; i < NE / 4; i++) {
            float4 ev = emb[i], yv = yv4[i];
            acc += ev.x * yv.x + ev.y * yv.y + ev.z * yv.z + ev.w * yv.w;
        }
        float mask = (idx != 0) ? 1.f : 0.f;
        out[(size_t)NB * 56 + (size_t)b * NKG + k] = sigmoidf_(acc) * mask;
        out[(size_t)NB * 64 + (size_t)b * NKG + k] = sc;
    } else if (tid < 64 + 160) {                  // 8 rows x 20 aroma slots
        const int task = tid - 64;
        const int r = task / NKA, k = task % NKA;
        const int b = b0 + r;
        const int   idx = aromas[b * NKA + k];
        const float sc  = aromas_scales[b * NKA + k];
        const float4* emb = reinterpret_cast<const float4*>(aroma_emb) + (size_t)idx * (NE / 4);
        const float4* yv4 = reinterpret_cast<const float4*>(&ya_sm[r * NE]);
        float acc = 0.f;
        #pragma unroll
        for (int i = 0; i < NE / 4; i++) {
            float4 ev = emb[i], yv = yv4[i];
            acc += ev.x * yv.x + ev.y * yv.y + ev.z * yv.z + ev.w * yv.w;
        }
        float mask = (sc != 0.f) ? 1.f : 0.f;
        out[(size_t)NB * 72 + (size_t)b * NKA + k] = sigmoidf_(acc) * mask;
        out[(size_t)NB * 92 + (size_t)b * NKA + k] = sc;
    }
}

extern "C" void kernel_launch(void* const* d_in, const int* in_sizes, int n_in,
                              void* d_out, int out_size) {
    const float* x_enc          = (const float*)d_in[0];
    const int*   grapes         = (const int*)  d_in[1];
    const float* grapes_scales  = (const float*)d_in[2];
    const int*   aromas         = (const int*)  d_in[3];
    const float* aromas_scales  = (const float*)d_in[4];
    const float* W_common       = (const float*)d_in[5];
    const float* b_common       = (const float*)d_in[6];
    const float* W_country      = (const float*)d_in[7];
    const float* b_country      = (const float*)d_in[8];
    const float* W_type         = (const float*)d_in[9];
    const float* b_type         = (const float*)d_in[10];
    const float* W_taste        = (const float*)d_in[11];
    const float* b_taste        = (const float*)d_in[12];
    const float* W_aroma        = (const float*)d_in[13];
    const float* b_aroma        = (const float*)d_in[14];
    const float* W_grape        = (const float*)d_in[15];
    const float* b_grape        = (const float*)d_in[16];
    const float* grapes_emb     = (const float*)d_in[17];
    const float* aroma_emb      = (const float*)d_in[18];
    float* out = (float*)d_out;

    wine_fused<<<NB / 8, 512>>>(reinterpret_cast<const float4*>(x_enc),
                                grapes, grapes_scales, aromas, aromas_scales,
                                W_common, b_common, W_country, b_country,
                                W_type, b_type, W_taste, b_taste,
                                W_aroma, b_aroma, W_grape, b_grape,
                                grapes_emb, aroma_emb, out);
}

// round 4
// speedup vs baseline: 2.0852x; 1.1071x over previous
#include <cuda_runtime.h>
#include <math.h>

#define NB 4096
#define NS 64
#define NY 256
#define NH 128
#define NE 32
#define NKG 8
#define NKA 20
#define NNC 50
#define NNT 5

__device__ __forceinline__ float sigmoidf_(float v) { return 1.f / (1.f + expf(-v)); }

// One block = 8 batch rows, 256 threads, 4 blocks/SM -> 512 blocks = single wave.
__global__ __launch_bounds__(256, 4) void wine_fused(
    const float4* __restrict__ x4,
    const int*   __restrict__ grapes,
    const float* __restrict__ grapes_scales,
    const int*   __restrict__ aromas,
    const float* __restrict__ aromas_scales,
    const float* __restrict__ W_common, const float* __restrict__ b_common,
    const float* __restrict__ W_country, const float* __restrict__ b_country,
    const float* __restrict__ W_type,   const float* __restrict__ b_type,
    const float* __restrict__ W_taste,  const float* __restrict__ b_taste,
    const float* __restrict__ W_aroma,  const float* __restrict__ b_aroma,
    const float* __restrict__ W_grape,  const float* __restrict__ b_grape,
    const float* __restrict__ grapes_emb,
    const float* __restrict__ aroma_emb,
    float* __restrict__ out)
{
    __shared__ __align__(16) float x_sm[8 * NY];       // 8 KB
    __shared__ float red[2][128][9];                   // 9.2 KB, padded banks
    __shared__ __align__(16) float y_sm[8 * NH];       // 4 KB
    __shared__ __align__(16) float yg_sm[8 * NE];      // 1 KB
    __shared__ __align__(16) float ya_sm[8 * NE];      // 1 KB

    const int tid = threadIdx.x;
    const int b0  = blockIdx.x * 8;

    // ---------- Phase 1: max-pool. 512 (row, col4) tasks, 2 per thread, private chains ----------
    #pragma unroll
    for (int q = 0; q < 2; q++) {
        const int task = tid + q * 256;
        const int r  = task >> 6;    // 0..7
        const int c4 = task & 63;    // 0..63
        const float4* p = x4 + (size_t)(b0 + r) * (NS * NY / 4) + c4;
        float4 m0 = p[0 * 64], m1 = p[1 * 64], m2 = p[2 * 64], m3 = p[3 * 64];
        #pragma unroll
        for (int s = 4; s < NS; s += 4) {
            float4 v0 = p[(s + 0) * 64];
            float4 v1 = p[(s + 1) * 64];
            float4 v2 = p[(s + 2) * 64];
            float4 v3 = p[(s + 3) * 64];
            m0.x = fmaxf(m0.x, v0.x); m0.y = fmaxf(m0.y, v0.y); m0.z = fmaxf(m0.z, v0.z); m0.w = fmaxf(m0.w, v0.w);
            m1.x = fmaxf(m1.x, v1.x); m1.y = fmaxf(m1.y, v1.y); m1.z = fmaxf(m1.z, v1.z); m1.w = fmaxf(m1.w, v1.w);
            m2.x = fmaxf(m2.x, v2.x); m2.y = fmaxf(m2.y, v2.y); m2.z = fmaxf(m2.z, v2.z); m2.w = fmaxf(m2.w, v2.w);
            m3.x = fmaxf(m3.x, v3.x); m3.y = fmaxf(m3.y, v3.y); m3.z = fmaxf(m3.z, v3.z); m3.w = fmaxf(m3.w, v3.w);
        }
        float4 rr;
        rr.x = fmaxf(fmaxf(m0.x, m1.x), fmaxf(m2.x, m3.x));
        rr.y = fmaxf(fmaxf(m0.y, m1.y), fmaxf(m2.y, m3.y));
        rr.z = fmaxf(fmaxf(m0.z, m1.z), fmaxf(m2.z, m3.z));
        rr.w = fmaxf(fmaxf(m0.w, m1.w), fmaxf(m2.w, m3.w));
        reinterpret_cast<float4*>(x_sm)[r * (NY / 4) + c4] = rr;
    }
    __syncthreads();

    // ---------- Phase 2: GEMM1 y[8][128] = elu(x[8][256] @ W_common + b), split-K x2 ----------
    {
        const int h  = tid & 127;
        const int kq = tid >> 7;          // 0..1, owns K range [kq*128, kq*128+128)
        float acc[8];
        #pragma unroll
        for (int j = 0; j < 8; j++) acc[j] = 0.f;
        const int kb = kq * 128;
        for (int i0 = 0; i0 < 128; i0 += 4) {
            const int i = kb + i0;
            float w0 = W_common[(i + 0) * NH + h];
            float w1 = W_common[(i + 1) * NH + h];
            float w2 = W_common[(i + 2) * NH + h];
            float w3 = W_common[(i + 3) * NH + h];
            #pragma unroll
            for (int j = 0; j < 8; j++) {
                float4 xv = *reinterpret_cast<const float4*>(&x_sm[j * NY + i]);
                acc[j] = fmaf(xv.x, w0, fmaf(xv.y, w1, fmaf(xv.z, w2, fmaf(xv.w, w3, acc[j]))));
            }
        }
        #pragma unroll
        for (int j = 0; j < 8; j++) red[kq][h][j] = acc[j];
    }
    __syncthreads();
    if (tid < NH) {
        const int h = tid;
        float bb = b_common[h];
        #pragma unroll
        for (int j = 0; j < 8; j++) {
            float v = red[0][h][j] + red[1][h][j] + bb;
            y_sm[j * NH + h] = (v > 0.f) ? v : expm1f(v);
        }
    }
    __syncthreads();

    // ---------- Phase 3: all heads as one 128x120 GEMM, split-K x2 ----------
    {
        const int c  = tid & 127;
        const int kq = tid >> 7;
        const int kb = kq * 64;           // K range [kb, kb+64) of NH=128
        float acc[8];
        #pragma unroll
        for (int j = 0; j < 8; j++) acc[j] = 0.f;

        if (c < NNC) {
            for (int i = kb; i < kb + 64; i += 4) {
                float w0 = W_country[(i + 0) * NNC + c];
                float w1 = W_country[(i + 1) * NNC + c];
                float w2 = W_country[(i + 2) * NNC + c];
                float w3 = W_country[(i + 3) * NNC + c];
                #pragma unroll
                for (int j = 0; j < 8; j++) {
                    float4 yv = *reinterpret_cast<const float4*>(&y_sm[j * NH + i]);
                    acc[j] = fmaf(yv.x, w0, fmaf(yv.y, w1, fmaf(yv.z, w2, fmaf(yv.w, w3, acc[j]))));
                }
            }
        } else if (c == NNC) {
            for (int i = kb; i < kb + 64; i += 4) {
                float w0 = W_type[i + 0], w1 = W_type[i + 1], w2 = W_type[i + 2], w3 = W_type[i + 3];
                #pragma unroll
                for (int j = 0; j < 8; j++) {
                    float4 yv = *reinterpret_cast<const float4*>(&y_sm[j * NH + i]);
                    acc[j] = fmaf(yv.x, w0, fmaf(yv.y, w1, fmaf(yv.z, w2, fmaf(yv.w, w3, acc[j]))));
                }
            }
        } else if (c < 56) {
            const int cc = c - 51;
            for (int i = kb; i < kb + 64; i += 4) {
                float w0 = W_taste[(i + 0) * NNT + cc];
                float w1 = W_taste[(i + 1) * NNT + cc];
                float w2 = W_taste[(i + 2) * NNT + cc];
                float w3 = W_taste[(i + 3) * NNT + cc];
                #pragma unroll
                for (int j = 0; j < 8; j++) {
                    float4 yv = *reinterpret_cast<const float4*>(&y_sm[j * NH + i]);
                    acc[j] = fmaf(yv.x, w0, fmaf(yv.y, w1, fmaf(yv.z, w2, fmaf(yv.w, w3, acc[j]))));
                }
            }
        } else if (c < 88) {
            const int e = c - 56;
            for (int i = kb; i < kb + 64; i += 4) {
                float w0 = W_grape[(i + 0) * NE + e];
                float w1 = W_grape[(i + 1) * NE + e];
                float w2 = W_grape[(i + 2) * NE + e];
                float w3 = W_grape[(i + 3) * NE + e];
                #pragma unroll
                for (int j = 0; j < 8; j++) {
                    float4 yv = *reinterpret_cast<const float4*>(&y_sm[j * NH + i]);
                    acc[j] = fmaf(yv.x, w0, fmaf(yv.y, w1, fmaf(yv.z, w2, fmaf(yv.w, w3, acc[j]))));
                }
            }
        } else if (c < 120) {
            const int e = c - 88;
            for (int i = kb; i < kb + 64; i += 4) {
                float w0 = W_aroma[(i + 0) * NE + e];
                float w1 = W_aroma[(i + 1) * NE + e];
                float w2 = W_aroma[(i + 2) * NE + e];
                float w3 = W_aroma[(i + 3) * NE + e];
                #pragma unroll
                for (int j = 0; j < 8; j++) {
                    float4 yv = *reinterpret_cast<const float4*>(&y_sm[j * NH + i]);
                    acc[j] = fmaf(yv.x, w0, fmaf(yv.y, w1, fmaf(yv.z, w2, fmaf(yv.w, w3, acc[j]))));
                }
            }
        }
        if (c < 120) {
            #pragma unroll
            for (int j = 0; j < 8; j++) red[kq][c][j] = acc[j];
        }
    }
    __syncthreads();
    if (tid < 120) {
        const int c = tid;
        float s[8];
        #pragma unroll
        for (int j = 0; j < 8; j++)
            s[j] = red[0][c][j] + red[1][c][j];
        if (c < NNC) {
            float bb = b_country[c];
            #pragma unroll
            for (int j = 0; j < 8; j++)
                out[(size_t)(b0 + j) * NNC + c] = s[j] + bb;
        } else if (c == NNC) {
            float bb = b_type[0];
            #pragma unroll
            for (int j = 0; j < 8; j++)
                out[(size_t)NB * NNC + (b0 + j)] = sigmoidf_(s[j] + bb);
        } else if (c < 56) {
            const int cc = c - 51;
            float bb = b_taste[cc];
            #pragma unroll
            for (int j = 0; j < 8; j++)
                out[(size_t)NB * 51 + (size_t)(b0 + j) * NNT + cc] = sigmoidf_(s[j] + bb);
        } else if (c < 88) {
            const int e = c - 56;
            float bb = b_grape[e];
            #pragma unroll
            for (int j = 0; j < 8; j++) yg_sm[j * NE + e] = s[j] + bb;
        } else {
            const int e = c - 88;
            float bb = b_aroma[e];
            #pragma unroll
            for (int j = 0; j < 8; j++) ya_sm[j * NE + e] = s[j] + bb;
        }
    }
    __syncthreads();

    // ---------- Phase 4: ragged embedding scoring (224 tasks over 256 threads) ----------
    if (tid < 64) {                               // 8 rows x 8 grape slots
        const int r = tid >> 3, k = tid & 7;
        const int b = b0 + r;
        const int   idx = grapes[b * NKG + k];
        const float sc  = grapes_scales[b * NKG + k];
        const float4* emb = reinterpret_cast<const float4*>(grapes_emb) + (size_t)idx * (NE / 4);
        const float4* yv4 = reinterpret_cast<const float4*>(&yg_sm[r * NE]);
        float acc = 0.f;
        #pragma unroll
        for (int i = 0; i < NE / 4; i++) {
            float4 ev = emb[i], yv = yv4[i];
            acc += ev.x * yv.x + ev.y * yv.y + ev.z * yv.z + ev.w * yv.w;
        }
        float mask = (idx != 0) ? 1.f : 0.f;
        out[(size_t)NB * 56 + (size_t)b * NKG + k] = sigmoidf_(acc) * mask;
        out[(size_t)NB * 64 + (size_t)b * NKG + k] = sc;
    } else if (tid < 64 + 160) {                  // 8 rows x 20 aroma slots
        const int task = tid - 64;
        const int r = task / NKA, k = task % NKA;
        const int b = b0 + r;
        const int   idx = aromas[b * NKA + k];
        const float sc  = aromas_scales[b * NKA + k];
        const float4* emb = reinterpret_cast<const float4*>(aroma_emb) + (size_t)idx * (NE / 4);
        const float4* yv4 = reinterpret_cast<const float4*>(&ya_sm[r * NE]);
        float acc = 0.f;
        #pragma unroll
        for (int i = 0; i < NE / 4; i++) {
            float4 ev = emb[i], yv = yv4[i];
            acc += ev.x * yv.x + ev.y * yv.y + ev.z * yv.z + ev.w * yv.w;
        }
        float mask = (sc != 0.f) ? 1.f : 0.f;
        out[(size_t)NB * 72 + (size_t)b * NKA + k] = sigmoidf_(acc) * mask;
        out[(size_t)NB * 92 + (size_t)b * NKA + k] = sc;
    }
}

extern "C" void kernel_launch(void* const* d_in, const int* in_sizes, int n_in,
                              void* d_out, int out_size) {
    const float* x_enc          = (const float*)d_in[0];
    const int*   grapes         = (const int*)  d_in[1];
    const float* grapes_scales  = (const float*)d_in[2];
    const int*   aromas         = (const int*)  d_in[3];
    const float* aromas_scales  = (const float*)d_in[4];
    const float* W_common       = (const float*)d_in[5];
    const float* b_common       = (const float*)d_in[6];
    const float* W_country      = (const float*)d_in[7];
    const float* b_country      = (const float*)d_in[8];
    const float* W_type         = (const float*)d_in[9];
    const float* b_type         = (const float*)d_in[10];
    const float* W_taste        = (const float*)d_in[11];
    const float* b_taste        = (const float*)d_in[12];
    const float* W_aroma        = (const float*)d_in[13];
    const float* b_aroma        = (const float*)d_in[14];
    const float* W_grape        = (const float*)d_in[15];
    const float* b_grape        = (const float*)d_in[16];
    const float* grapes_emb     = (const float*)d_in[17];
    const float* aroma_emb      = (const float*)d_in[18];
    float* out = (float*)d_out;

    wine_fused<<<NB / 8, 256>>>(reinterpret_cast<const float4*>(x_enc),
                                grapes, grapes_scales, aromas, aromas_scales,
                                W_common, b_common, W_country, b_country,
                                W_type, b_type, W_taste, b_taste,
                                W_aroma, b_aroma, W_grape, b_grape,
                                grapes_emb, aroma_emb, out);
}

// round 5
// speedup vs baseline: 2.2220x; 1.0656x over previous
#include <cuda_runtime.h>
#include <math.h>

#define NB 4096
#define NS 64
#define NY 256
#define NH 128
#define NE 32
#define NKG 8
#define NKA 20
#define NNC 50
#define NNT 5

typedef unsigned long long ull;

__device__ __forceinline__ float sigmoidf_(float v) { return 1.f / (1.f + expf(-v)); }

#define FMA2(acc, a, b) asm("fma.rn.f32x2 %0, %1, %2, %0;" : "+l"(acc) : "l"(a), "l"(b))
#define PACK2(out, lo, hi) asm("mov.b64 %0, {%1, %2};" : "=l"(out) : "f"(lo), "f"(hi))
#define UNPACK2(lo, hi, in) asm("mov.b64 {%0, %1}, %2;" : "=f"(lo), "=f"(hi) : "l"(in))

// One block = 8 batch rows, 256 threads, 4 blocks/SM -> 512 blocks = single wave.
__global__ __launch_bounds__(256, 4) void wine_fused(
    const float4* __restrict__ x4,
    const int*   __restrict__ grapes,
    const float* __restrict__ grapes_scales,
    const int*   __restrict__ aromas,
    const float* __restrict__ aromas_scales,
    const float* __restrict__ W_common, const float* __restrict__ b_common,
    const float* __restrict__ W_country, const float* __restrict__ b_country,
    const float* __restrict__ W_type,   const float* __restrict__ b_type,
    const float* __restrict__ W_taste,  const float* __restrict__ b_taste,
    const float* __restrict__ W_aroma,  const float* __restrict__ b_aroma,
    const float* __restrict__ W_grape,  const float* __restrict__ b_grape,
    const float* __restrict__ grapes_emb,
    const float* __restrict__ aroma_emb,
    float* __restrict__ out)
{
    __shared__ __align__(16) float x_sm[8 * NY];       // 8 KB
    __shared__ float red[2][128][9];                   // 9.2 KB, padded banks
    __shared__ __align__(16) float y_sm[8 * NH];       // 4 KB
    __shared__ __align__(16) float yg_sm[8 * NE];      // 1 KB
    __shared__ __align__(16) float ya_sm[8 * NE];      // 1 KB

    const int tid = threadIdx.x;
    const int b0  = blockIdx.x * 8;

    // ---------- Phase 1: max-pool. 512 (row, col4) tasks, 2 per thread ----------
    #pragma unroll
    for (int q = 0; q < 2; q++) {
        const int task = tid + q * 256;
        const int r  = task >> 6;
        const int c4 = task & 63;
        const float4* p = x4 + (size_t)(b0 + r) * (NS * NY / 4) + c4;
        float4 m0 = p[0 * 64], m1 = p[1 * 64], m2 = p[2 * 64], m3 = p[3 * 64];
        #pragma unroll
        for (int s = 4; s < NS; s += 4) {
            float4 v0 = p[(s + 0) * 64];
            float4 v1 = p[(s + 1) * 64];
            float4 v2 = p[(s + 2) * 64];
            float4 v3 = p[(s + 3) * 64];
            m0.x = fmaxf(m0.x, v0.x); m0.y = fmaxf(m0.y, v0.y); m0.z = fmaxf(m0.z, v0.z); m0.w = fmaxf(m0.w, v0.w);
            m1.x = fmaxf(m1.x, v1.x); m1.y = fmaxf(m1.y, v1.y); m1.z = fmaxf(m1.z, v1.z); m1.w = fmaxf(m1.w, v1.w);
            m2.x = fmaxf(m2.x, v2.x); m2.y = fmaxf(m2.y, v2.y); m2.z = fmaxf(m2.z, v2.z); m2.w = fmaxf(m2.w, v2.w);
            m3.x = fmaxf(m3.x, v3.x); m3.y = fmaxf(m3.y, v3.y); m3.z = fmaxf(m3.z, v3.z); m3.w = fmaxf(m3.w, v3.w);
        }
        float4 rr;
        rr.x = fmaxf(fmaxf(m0.x, m1.x), fmaxf(m2.x, m3.x));
        rr.y = fmaxf(fmaxf(m0.y, m1.y), fmaxf(m2.y, m3.y));
        rr.z = fmaxf(fmaxf(m0.z, m1.z), fmaxf(m2.z, m3.z));
        rr.w = fmaxf(fmaxf(m0.w, m1.w), fmaxf(m2.w, m3.w));
        reinterpret_cast<float4*>(x_sm)[r * (NY / 4) + c4] = rr;
    }
    __syncthreads();

    // ---------- Phase 2: GEMM1 y[8][128] = elu(x @ W_common + b), split-K x2, f32x2 ----------
    {
        const int h  = tid & 127;
        const int kq = tid >> 7;
        const int kb = kq * 128;
        ull acc2[8];
        #pragma unroll
        for (int j = 0; j < 8; j++) acc2[j] = 0ull;
        #pragma unroll 4
        for (int i = kb; i < kb + 128; i += 4) {
            float wa0 = W_common[(i + 0) * NH + h];
            float wa1 = W_common[(i + 1) * NH + h];
            float wb0 = W_common[(i + 2) * NH + h];
            float wb1 = W_common[(i + 3) * NH + h];
            ull wpa, wpb;
            PACK2(wpa, wa0, wa1);
            PACK2(wpb, wb0, wb1);
            #pragma unroll
            for (int j = 0; j < 8; j++) {
                ulonglong2 xv = *reinterpret_cast<const ulonglong2*>(&x_sm[j * NY + i]);
                FMA2(acc2[j], xv.x, wpa);
                FMA2(acc2[j], xv.y, wpb);
            }
        }
        #pragma unroll
        for (int j = 0; j < 8; j++) {
            float lo, hi;
            UNPACK2(lo, hi, acc2[j]);
            red[kq][h][j] = lo + hi;
        }
    }
    __syncthreads();
    if (tid < NH) {
        const int h = tid;
        float bb = b_common[h];
        #pragma unroll
        for (int j = 0; j < 8; j++) {
            float v = red[0][h][j] + red[1][h][j] + bb;
            y_sm[j * NH + h] = (v > 0.f) ? v : expm1f(v);
        }
    }
    __syncthreads();

    // ---------- Phase 3: all heads as one 128x120 GEMM, split-K x2, f32x2 ----------
    {
        const int c  = tid & 127;
        const int kq = tid >> 7;
        const int kb = kq * 64;
        ull acc2[8];
        #pragma unroll
        for (int j = 0; j < 8; j++) acc2[j] = 0ull;

        const float* Wp; int stride; int cc = c;
        if (c < NNC)       { Wp = W_country; stride = NNC; }
        else if (c == NNC) { Wp = W_type;    stride = 1;  cc = 0; }
        else if (c < 56)   { Wp = W_taste;   stride = NNT; cc = c - 51; }
        else if (c < 88)   { Wp = W_grape;   stride = NE;  cc = c - 56; }
        else if (c < 120)  { Wp = W_aroma;   stride = NE;  cc = c - 88; }
        else               { Wp = W_country; stride = NNC; cc = 0; }   // dummy lanes

        #pragma unroll 4
        for (int i = kb; i < kb + 64; i += 4) {
            float wa0 = Wp[(i + 0) * stride + cc];
            float wa1 = Wp[(i + 1) * stride + cc];
            float wb0 = Wp[(i + 2) * stride + cc];
            float wb1 = Wp[(i + 3) * stride + cc];
            ull wpa, wpb;
            PACK2(wpa, wa0, wa1);
            PACK2(wpb, wb0, wb1);
            #pragma unroll
            for (int j = 0; j < 8; j++) {
                ulonglong2 yv = *reinterpret_cast<const ulonglong2*>(&y_sm[j * NH + i]);
                FMA2(acc2[j], yv.x, wpa);
                FMA2(acc2[j], yv.y, wpb);
            }
        }
        if (c < 120) {
            #pragma unroll
            for (int j = 0; j < 8; j++) {
                float lo, hi;
                UNPACK2(lo, hi, acc2[j]);
                red[kq][c][j] = lo + hi;
            }
        }
    }
    __syncthreads();
    if (tid < 120) {
        const int c = tid;
        float s[8];
        #pragma unroll
        for (int j = 0; j < 8; j++)
            s[j] = red[0][c][j] + red[1][c][j];
        if (c < NNC) {
            float bb = b_country[c];
            #pragma unroll
            for (int j = 0; j < 8; j++)
                out[(size_t)(b0 + j) * NNC + c] = s[j] + bb;
        } else if (c == NNC) {
            float bb = b_type[0];
            #pragma unroll
            for (int j = 0; j < 8; j++)
                out[(size_t)NB * NNC + (b0 + j)] = sigmoidf_(s[j] + bb);
        } else if (c < 56) {
            const int cc = c - 51;
            float bb = b_taste[cc];
            #pragma unroll
            for (int j = 0; j < 8; j++)
                out[(size_t)NB * 51 + (size_t)(b0 + j) * NNT + cc] = sigmoidf_(s[j] + bb);
        } else if (c < 88) {
            const int e = c - 56;
            float bb = b_grape[e];
            #pragma unroll
            for (int j = 0; j < 8; j++) yg_sm[j * NE + e] = s[j] + bb;
        } else {
            const int e = c - 88;
            float bb = b_aroma[e];
            #pragma unroll
            for (int j = 0; j < 8; j++) ya_sm[j * NE + e] = s[j] + bb;
        }
    }
    __syncthreads();

    // ---------- Phase 4: ragged embedding scoring ----------
    if (tid < 64) {                               // 8 rows x 8 grape slots
        const int r = tid >> 3, k = tid & 7;
        const int b = b0 + r;
        const int   idx = grapes[b * NKG + k];
        const float sc  = grapes_scales[b * NKG + k];
        const float4* emb = reinterpret_cast<const float4*>(grapes_emb) + (size_t)idx * (NE / 4);
        const float4* yv4 = reinterpret_cast<const float4*>(&yg_sm[r * NE]);
        float acc = 0.f;
        #pragma unroll
        for (int i = 0; i < NE / 4; i++) {
            float4 ev = emb[i], yv = yv4[i];
            acc += ev.x * yv.x + ev.y * yv.y + ev.z * yv.z + ev.w * yv.w;
        }
        float mask = (idx != 0) ? 1.f : 0.f;
        out[(size_t)NB * 56 + (size_t)b * NKG + k] = sigmoidf_(acc) * mask;
        out[(size_t)NB * 64 + (size_t)b * NKG + k] = sc;
    } else if (tid < 64 + 160) {                  // 8 rows x 20 aroma slots
        const int task = tid - 64;
        const int r = task / NKA, k = task % NKA;
        const int b = b0 + r;
        const int   idx = aromas[b * NKA + k];
        const float sc  = aromas_scales[b * NKA + k];
        const float4* emb = reinterpret_cast<const float4*>(aroma_emb) + (size_t)idx * (NE / 4);
        const float4* yv4 = reinterpret_cast<const float4*>(&ya_sm[r * NE]);
        float acc = 0.f;
        #pragma unroll
        for (int i = 0; i < NE / 4; i++) {
            float4 ev = emb[i], yv = yv4[i];
            acc += ev.x * yv.x + ev.y * yv.y + ev.z * yv.z + ev.w * yv.w;
        }
        float mask = (sc != 0.f) ? 1.f : 0.f;
        out[(size_t)NB * 72 + (size_t)b * NKA + k] = sigmoidf_(acc) * mask;
        out[(size_t)NB * 92 + (size_t)b * NKA + k] = sc;
    }
}

extern "C" void kernel_launch(void* const* d_in, const int* in_sizes, int n_in,
                              void* d_out, int out_size) {
    const float* x_enc          = (const float*)d_in[0];
    const int*   grapes         = (const int*)  d_in[1];
    const float* grapes_scales  = (const float*)d_in[2];
    const int*   aromas         = (const int*)  d_in[3];
    const float* aromas_scales  = (const float*)d_in[4];
    const float* W_common       = (const float*)d_in[5];
    const float* b_common       = (const float*)d_in[6];
    const float* W_country      = (const float*)d_in[7];
    const float* b_country      = (const float*)d_in[8];
    const float* W_type         = (const float*)d_in[9];
    const float* b_type         = (const float*)d_in[10];
    const float* W_taste        = (const float*)d_in[11];
    const float* b_taste        = (const float*)d_in[12];
    const float* W_aroma        = (const float*)d_in[13];
    const float* b_aroma        = (const float*)d_in[14];
    const float* W_grape        = (const float*)d_in[15];
    const float* b_grape        = (const float*)d_in[16];
    const float* grapes_emb     = (const float*)d_in[17];
    const float* aroma_emb      = (const float*)d_in[18];
    float* out = (float*)d_out;

    wine_fused<<<NB / 8, 256>>>(reinterpret_cast<const float4*>(x_enc),
                                grapes, grapes_scales, aromas, aromas_scales,
                                W_common, b_common, W_country, b_country,
                                W_type, b_type, W_taste, b_taste,
                                W_aroma, b_aroma, W_grape, b_grape,
                                grapes_emb, aroma_emb, out);
}